// round 7
// baseline (speedup 1.0000x reference)
#include <cuda_runtime.h>
#include <cuda_bf16.h>
#include <cuda_fp16.h>
#include <cstdint>
#include <math.h>

#define BB 64
#define CC 2048
#define CI 1024
#define NSP 512   // H*W

typedef unsigned short u16;
typedef uint32_t u32;

// ---------------- scratch (static device globals) -----------------------------
__device__ u16 g_xTbh[(size_t)BB * NSP * CC];
__device__ u16 g_xTbl[(size_t)BB * NSP * CC];
__device__ u16 g_xTf [(size_t)BB * NSP * CC];
__device__ u16 g_Wth[(size_t)CI * CC], g_Wtl[(size_t)CI * CC];
__device__ u16 g_Wph[(size_t)CI * CC], g_Wpl[(size_t)CI * CC];
__device__ u16 g_Wgh[(size_t)CI * CC], g_Wgl[(size_t)CI * CC];
__device__ u16 g_Woh[(size_t)CC * CI], g_Wol[(size_t)CC * CI];
__device__ u16 g_thh[(size_t)BB * NSP * CI], g_thl[(size_t)BB * NSP * CI];
__device__ u16 g_phh[(size_t)BB * NSP * CI], g_phl[(size_t)BB * NSP * CI];
__device__ u16 g_gf [(size_t)BB * CI * NSP];
__device__ float g_f [(size_t)BB * NSP * NSP];
__device__ u16 g_ath[(size_t)BB * NSP * NSP], g_atl[(size_t)BB * NSP * NSP];
__device__ u16 g_yT [(size_t)BB * NSP * CI];
__device__ float g_mean[CC];
__device__ float g_rstd[CC];

// ---------------- helpers ------------------------------------------------------
__device__ __forceinline__ u32 smem_u32(const void* p) {
    u32 a;
    asm("{ .reg .u64 t; cvta.to.shared.u64 t, %1; cvt.u32.u64 %0, t; }" : "=r"(a) : "l"(p));
    return a;
}
__device__ __forceinline__ void split_bf(float v, u16& h, u16& l) {
    __nv_bfloat16 bh = __float2bfloat16(v);
    h = __bfloat16_as_ushort(bh);
    l = __bfloat16_as_ushort(__float2bfloat16(v - __bfloat162float(bh)));
}
__device__ __forceinline__ void split_fp(float v, u16& h, u16& l) {
    __half hh = __float2half_rn(v);
    h = __half_as_ushort(hh);
    l = __half_as_ushort(__float2half_rn(v - __half2float(hh)));
}
__device__ __forceinline__ void ldsm_x4(u32* r, u32 addr) {
    asm volatile("ldmatrix.sync.aligned.m8n8.x4.shared.b16 {%0,%1,%2,%3}, [%4];"
                 : "=r"(r[0]), "=r"(r[1]), "=r"(r[2]), "=r"(r[3]) : "r"(addr));
}
template<int FP16>
__device__ __forceinline__ void mma16816(float* c, const u32* a, u32 b0, u32 b1) {
    if (FP16)
        asm volatile("mma.sync.aligned.m16n8k16.row.col.f32.f16.f16.f32 "
                     "{%0,%1,%2,%3}, {%4,%5,%6,%7}, {%8,%9}, {%0,%1,%2,%3};"
                     : "+f"(c[0]), "+f"(c[1]), "+f"(c[2]), "+f"(c[3])
                     : "r"(a[0]), "r"(a[1]), "r"(a[2]), "r"(a[3]), "r"(b0), "r"(b1));
    else
        asm volatile("mma.sync.aligned.m16n8k16.row.col.f32.bf16.bf16.f32 "
                     "{%0,%1,%2,%3}, {%4,%5,%6,%7}, {%8,%9}, {%0,%1,%2,%3};"
                     : "+f"(c[0]), "+f"(c[1]), "+f"(c[2]), "+f"(c[3])
                     : "r"(a[0]), "r"(a[1]), "r"(a[2]), "r"(a[3]), "r"(b0), "r"(b1));
}

// copy ROWSx32 u16 chunk (row stride K) into blocked smem layout
template<int ROWS>
__device__ __forceinline__ void cpa(u32 dst, const u16* __restrict__ src,
                                    int K, int k0, int tid) {
    constexpr int RT  = ROWS / 8;
    constexpr int PER = (ROWS * 4) / 256;
#pragma unroll
    for (int i = 0; i < PER; ++i) {
        int u  = tid + i * 256;
        int r  = u >> 2;
        int kb = u & 3;
        const void* gp = src + (size_t)r * K + k0 + kb * 8;
        u32 dp = dst + (u32)(((kb * RT + (r >> 3)) << 7) + ((r & 7) << 4));
        asm volatile("cp.async.cg.shared.global [%0], [%1], 16;" :: "r"(dp), "l"(gp));
    }
}

// ---------------- HMMA GEMM -----------------------------------------------------
// D[m][n] = sum_k A[m][k]*B[n][k]. A hi/lo split always.
// NMMA=3: +AhBl (B split).  NMMA=2: B single.
// CTA 128x256, 8 warps (2m x 4n), warp 64x64, k-chunk 32, 4 stages, 1 CTA/SM.
// MMA issue order: per np-group, three passes of 8 INDEPENDENT MMAs so that
// dependent MMAs on the same accumulator are 8 issue slots apart.
// OUT: 0 fp32, 1 hi/lo pair, 2 single.  BIAS: 0 none, 1 row(M), 2 col(N).
template<int FP16, int NMMA, int OUT, int BIAS>
__global__ void __launch_bounds__(256, 1)
hgemm(const u16* __restrict__ Ah, const u16* __restrict__ Al,
      const u16* __restrict__ Bh, const u16* __restrict__ Bl,
      void* __restrict__ Co, u16* __restrict__ Colo,
      const float* __restrict__ bias,
      int K, int ldo, long bsA, long bsB, long bsC)
{
    extern __shared__ char smem[];
    const u32 sm0 = smem_u32(smem);
    constexpr u32 STAGE = (NMMA == 3) ? 49152u : 32768u;

    const int tid = threadIdx.x, lane = tid & 31, wid = tid >> 5;
    const int wm = wid >> 2, wn = wid & 3;
    const int m0 = blockIdx.y * 128, n0 = blockIdx.x * 256, b = blockIdx.z;

    const u16* pAh = Ah + (size_t)b * bsA + (size_t)m0 * K;
    const u16* pAl = Al + (size_t)b * bsA + (size_t)m0 * K;
    const u16* pBh = Bh + (size_t)b * bsB + (size_t)n0 * K;
    const u16* pBl = (NMMA == 3) ? (Bl + (size_t)b * bsB + (size_t)n0 * K) : nullptr;

    const int nch = K >> 5;

    float acc[4][8][4];
#pragma unroll
    for (int i = 0; i < 4; ++i)
#pragma unroll
        for (int j = 0; j < 8; ++j)
#pragma unroll
            for (int q = 0; q < 4; ++q) acc[i][j][q] = 0.f;

    // prologue: prefetch chunks 0..2
#pragma unroll
    for (int p = 0; p < 3; ++p) {
        u32 sb = sm0 + (u32)(p & 3) * STAGE;
        cpa<128>(sb,         pAh, K, p * 32, tid);
        cpa<128>(sb + 8192,  pAl, K, p * 32, tid);
        cpa<256>(sb + 16384, pBh, K, p * 32, tid);
        if (NMMA == 3) cpa<256>(sb + 32768, pBl, K, p * 32, tid);
        asm volatile("cp.async.commit_group;");
    }

    const int ga = lane >> 3;
    const int lrow = lane & 7;

    for (int ks = 0; ks < nch; ++ks) {
        asm volatile("cp.async.wait_group 2;" ::: "memory");
        __syncthreads();
        {
            const int pf = ks + 3;
            if (pf < nch) {
                u32 sb = sm0 + (u32)(pf & 3) * STAGE;
                cpa<128>(sb,         pAh, K, pf * 32, tid);
                cpa<128>(sb + 8192,  pAl, K, pf * 32, tid);
                cpa<256>(sb + 16384, pBh, K, pf * 32, tid);
                if (NMMA == 3) cpa<256>(sb + 32768, pBl, K, pf * 32, tid);
            }
            asm volatile("cp.async.commit_group;");
        }

        const u32 sb = sm0 + (u32)(ks & 3) * STAGE;
#pragma unroll
        for (int kk = 0; kk < 2; ++kk) {
            const int k8 = 2 * kk + (ga >> 1);
            // ---- A fragments (batched) ----
            u32 ah[4][4], al[4][4];
#pragma unroll
            for (int mf = 0; mf < 4; ++mf) {
                const int m8 = wm * 8 + mf * 2 + (ga & 1);
                u32 ad = sb + (u32)(((k8 * 16 + m8) << 7) + (lrow << 4));
                ldsm_x4(ah[mf], ad);
                ldsm_x4(al[mf], ad + 8192);
            }
            // ---- B fragments: double-buffered, prefetched one np ahead ----
            u32 bt[2][4], bs[2][4];
            {
                const int n8 = wn * 8 + (ga & 1);
                u32 bd = sb + 16384u + (u32)(((k8 * 32 + n8) << 7) + (lrow << 4));
                ldsm_x4(bt[0], bd);
                if (NMMA == 3) ldsm_x4(bs[0], bd + 16384u);
            }
#pragma unroll
            for (int np = 0; np < 4; ++np) {
                const int cur = np & 1;
                if (np < 3) {
                    const int n8 = wn * 8 + (np + 1) * 2 + (ga & 1);
                    u32 bd = sb + 16384u + (u32)(((k8 * 32 + n8) << 7) + (lrow << 4));
                    ldsm_x4(bt[cur ^ 1], bd);
                    if (NMMA == 3) ldsm_x4(bs[cur ^ 1], bd + 16384u);
                }
                // pass 1: ah * bt  (8 independent MMAs)
#pragma unroll
                for (int mf = 0; mf < 4; ++mf) {
                    mma16816<FP16>(acc[mf][2*np],   ah[mf], bt[cur][0], bt[cur][2]);
                    mma16816<FP16>(acc[mf][2*np+1], ah[mf], bt[cur][1], bt[cur][3]);
                }
                // pass 2: al * bt  (8 independent, each acc reused 8 slots later)
#pragma unroll
                for (int mf = 0; mf < 4; ++mf) {
                    mma16816<FP16>(acc[mf][2*np],   al[mf], bt[cur][0], bt[cur][2]);
                    mma16816<FP16>(acc[mf][2*np+1], al[mf], bt[cur][1], bt[cur][3]);
                }
                // pass 3 (NMMA==3): ah * bs
                if (NMMA == 3) {
#pragma unroll
                    for (int mf = 0; mf < 4; ++mf) {
                        mma16816<FP16>(acc[mf][2*np],   ah[mf], bs[cur][0], bs[cur][2]);
                        mma16816<FP16>(acc[mf][2*np+1], ah[mf], bs[cur][1], bs[cur][3]);
                    }
                }
            }
        }
    }

    // ---- epilogue ----
    const int erow = lane >> 2;
    const int ecol = (lane & 3) * 2;
#pragma unroll
    for (int mf = 0; mf < 4; ++mf) {
        const int gm = m0 + wm * 64 + mf * 16 + erow;
        float rb0 = 0.f, rb1 = 0.f;
        if (BIAS == 1) { rb0 = bias[gm]; rb1 = bias[gm + 8]; }
#pragma unroll
        for (int nf = 0; nf < 8; ++nf) {
            const int gn = n0 + wn * 64 + nf * 8 + ecol;
            float cb0 = 0.f, cb1 = 0.f;
            if (BIAS == 2) { cb0 = bias[gn]; cb1 = bias[gn + 1]; }
            float v00 = acc[mf][nf][0] + rb0 + cb0;
            float v01 = acc[mf][nf][1] + rb0 + cb1;
            float v10 = acc[mf][nf][2] + rb1 + cb0;
            float v11 = acc[mf][nf][3] + rb1 + cb1;
            if (OUT == 0) {
                float* C = (float*)Co + (size_t)b * bsC + (size_t)gm * ldo + gn;
                *reinterpret_cast<float2*>(C) = make_float2(v00, v01);
                *reinterpret_cast<float2*>(C + 8 * (size_t)ldo) = make_float2(v10, v11);
            } else if (OUT == 1) {
                u16* Ch = (u16*)Co + (size_t)b * bsC + (size_t)gm * ldo + gn;
                u16* Cl = Colo     + (size_t)b * bsC + (size_t)gm * ldo + gn;
                u16 h0, l0, h1, l1;
                if (FP16) { split_fp(v00, h0, l0); split_fp(v01, h1, l1); }
                else      { split_bf(v00, h0, l0); split_bf(v01, h1, l1); }
                *reinterpret_cast<u32*>(Ch) = (u32)h0 | ((u32)h1 << 16);
                *reinterpret_cast<u32*>(Cl) = (u32)l0 | ((u32)l1 << 16);
                if (FP16) { split_fp(v10, h0, l0); split_fp(v11, h1, l1); }
                else      { split_bf(v10, h0, l0); split_bf(v11, h1, l1); }
                *reinterpret_cast<u32*>(Ch + 8 * (size_t)ldo) = (u32)h0 | ((u32)h1 << 16);
                *reinterpret_cast<u32*>(Cl + 8 * (size_t)ldo) = (u32)l0 | ((u32)l1 << 16);
            } else {
                u16* C = (u16*)Co + (size_t)b * bsC + (size_t)gm * ldo + gn;
                u16 h0 = __half_as_ushort(__float2half_rn(v00));
                u16 h1 = __half_as_ushort(__float2half_rn(v01));
                *reinterpret_cast<u32*>(C) = (u32)h0 | ((u32)h1 << 16);
                h0 = __half_as_ushort(__float2half_rn(v10));
                h1 = __half_as_ushort(__float2half_rn(v11));
                *reinterpret_cast<u32*>(C + 8 * (size_t)ldo) = (u32)h0 | ((u32)h1 << 16);
            }
        }
    }
}

// ---------------- prepass: split all 4 weights in ONE launch -------------------
__global__ void __launch_bounds__(256)
wsplit_kernel(const float* __restrict__ Wt, const float* __restrict__ Wp,
              const float* __restrict__ Wg, const float* __restrict__ Wo,
              u16* wth, u16* wtl, u16* wph, u16* wpl,
              u16* wgh, u16* wgl, u16* woh, u16* wol)
{
    int i = blockIdx.x * 256 + threadIdx.x;
    u16 h, l;
    switch (blockIdx.y) {
        case 0: split_bf(Wt[i], h, l); wth[i] = h; wtl[i] = l; break;
        case 1: split_bf(Wp[i], h, l); wph[i] = h; wpl[i] = l; break;
        case 2: split_fp(Wg[i], h, l); wgh[i] = h; wgl[i] = l; break;
        default: split_fp(Wo[i], h, l); woh[i] = h; wol[i] = l; break;
    }
}

// x [b][c][n] -> xT bf16 h/l + fp16 single [b][n][c]
__global__ void __launch_bounds__(256)
xpose_split_kernel(const float* __restrict__ x, u16* __restrict__ bh,
                   u16* __restrict__ bl, u16* __restrict__ fh) {
    __shared__ float t[32][33];
    const int b = blockIdx.z;
    const int n0 = blockIdx.x * 32, c0 = blockIdx.y * 32;
    const int tx = threadIdx.x & 31, ty = threadIdx.x >> 5;
    const float* xp = x + ((size_t)b * CC + c0) * NSP + n0;
#pragma unroll
    for (int i = 0; i < 4; ++i)
        t[ty + i * 8][tx] = xp[(size_t)(ty + i * 8) * NSP + tx];
    __syncthreads();
    const size_t ob = ((size_t)b * NSP + n0) * CC + c0;
#pragma unroll
    for (int i = 0; i < 4; ++i) {
        float v = t[tx][ty + i * 8];
        size_t idx = ob + (size_t)(ty + i * 8) * CC + tx;
        u16 h, l;
        split_bf(v, h, l);
        bh[idx] = h; bl[idx] = l;
        fh[idx] = __half_as_ushort(__float2half_rn(v));
    }
}

// ---------------- softmax over rows of 512 -> fp16 hi/lo -----------------------
__global__ void __launch_bounds__(256)
softmax_split_kernel(const float* __restrict__ f, u16* __restrict__ ah,
                     u16* __restrict__ al) {
    const size_t off = (size_t)blockIdx.x * NSP;
    const float* p = f + off;
    const int t = threadIdx.x;
    float v0 = p[t];
    float v1 = p[t + 256];

    __shared__ float red[8];
    float m = fmaxf(v0, v1);
#pragma unroll
    for (int o = 16; o; o >>= 1) m = fmaxf(m, __shfl_xor_sync(0xffffffffu, m, o));
    if ((t & 31) == 0) red[t >> 5] = m;
    __syncthreads();
    float M = red[0];
#pragma unroll
    for (int i = 1; i < 8; ++i) M = fmaxf(M, red[i]);
    __syncthreads();

    float e0 = expf(v0 - M);
    float e1 = expf(v1 - M);
    float s = e0 + e1;
#pragma unroll
    for (int o = 16; o; o >>= 1) s += __shfl_xor_sync(0xffffffffu, s, o);
    if ((t & 31) == 0) red[t >> 5] = s;
    __syncthreads();
    float S = 0.f;
#pragma unroll
    for (int i = 0; i < 8; ++i) S += red[i];

    const float inv = 1.f / S;
    u16 h, l;
    split_fp(e0 * inv, h, l);  ah[off + t] = h;        al[off + t] = l;
    split_fp(e1 * inv, h, l);  ah[off + t + 256] = h;  al[off + t + 256] = l;
}

// ---------------- BN stats (fp32 accumulation) & apply --------------------------
__global__ void __launch_bounds__(256)
bn_stats_kernel(const float* __restrict__ wy, float* __restrict__ mean,
                float* __restrict__ rstd) {
    const int o = blockIdx.x;
    const int t = threadIdx.x;
    float ds = 0.f, dss = 0.f;
    for (int i = t; i < BB * NSP; i += 256) {
        const int b = i >> 9;
        const int n = i & (NSP - 1);
        const float v = wy[((size_t)b * CC + o) * NSP + n];
        ds  += v;
        dss = fmaf(v, v, dss);
    }
    __shared__ float r1[256];
    __shared__ float r2[256];
    r1[t] = ds; r2[t] = dss;
    __syncthreads();
    for (int st = 128; st; st >>= 1) {
        if (t < st) { r1[t] += r1[t + st]; r2[t] += r2[t + st]; }
        __syncthreads();
    }
    if (t == 0) {
        const double cnt = (double)(BB * NSP);
        const double mu  = (double)r1[0] / cnt;
        const double var = (double)r2[0] / cnt - mu * mu;
        mean[o] = (float)mu;
        rstd[o] = (float)rsqrt(var + 1e-5);
    }
}

__global__ void __launch_bounds__(256)
bn_apply_kernel(float* __restrict__ out, const float* __restrict__ x,
                const float* __restrict__ mean, const float* __restrict__ rstd,
                const float* __restrict__ gamma, const float* __restrict__ beta) {
    const long i4 = (long)blockIdx.x * blockDim.x + threadIdx.x;
    const long e = i4 * 4;
    const int c = (int)((e >> 9) & (CC - 1));
    const float mu = mean[c];
    const float rs = rstd[c];
    const float ga = gamma[c];
    const float be = beta[c];
    float4 w  = *reinterpret_cast<const float4*>(&out[e]);
    float4 xv = *reinterpret_cast<const float4*>(&x[e]);
    w.x = (w.x - mu) * rs * ga + be + xv.x;
    w.y = (w.y - mu) * rs * ga + be + xv.y;
    w.z = (w.z - mu) * rs * ga + be + xv.z;
    w.w = (w.w - mu) * rs * ga + be + xv.w;
    *reinterpret_cast<float4*>(&out[e]) = w;
}

// -------------------------------------------------------------------------------
extern "C" void kernel_launch(void* const* d_in, const int* in_sizes, int n_in,
                              void* d_out, int out_size)
{
    const float* x     = (const float*)d_in[0];
    const float* Wg    = (const float*)d_in[1];
    const float* bg    = (const float*)d_in[2];
    const float* Wt    = (const float*)d_in[3];
    const float* bt    = (const float*)d_in[4];
    const float* Wp    = (const float*)d_in[5];
    const float* bp    = (const float*)d_in[6];
    const float* Wo    = (const float*)d_in[7];
    const float* bo    = (const float*)d_in[8];
    const float* gamma = (const float*)d_in[9];
    const float* beta  = (const float*)d_in[10];
    float* out = (float*)d_out;

    u16 *xTbh, *xTbl, *xTf, *Wth, *Wtl, *Wph, *Wpl, *Wgh, *Wgl, *Woh, *Wol;
    u16 *thh, *thl, *phh, *phl, *gf, *ath, *atl, *yT;
    float *f, *mean, *rstd;
    cudaGetSymbolAddress((void**)&xTbh, g_xTbh); cudaGetSymbolAddress((void**)&xTbl, g_xTbl);
    cudaGetSymbolAddress((void**)&xTf,  g_xTf);
    cudaGetSymbolAddress((void**)&Wth, g_Wth); cudaGetSymbolAddress((void**)&Wtl, g_Wtl);
    cudaGetSymbolAddress((void**)&Wph, g_Wph); cudaGetSymbolAddress((void**)&Wpl, g_Wpl);
    cudaGetSymbolAddress((void**)&Wgh, g_Wgh); cudaGetSymbolAddress((void**)&Wgl, g_Wgl);
    cudaGetSymbolAddress((void**)&Woh, g_Woh); cudaGetSymbolAddress((void**)&Wol, g_Wol);
    cudaGetSymbolAddress((void**)&thh, g_thh); cudaGetSymbolAddress((void**)&thl, g_thl);
    cudaGetSymbolAddress((void**)&phh, g_phh); cudaGetSymbolAddress((void**)&phl, g_phl);
    cudaGetSymbolAddress((void**)&gf,  g_gf);
    cudaGetSymbolAddress((void**)&ath, g_ath); cudaGetSymbolAddress((void**)&atl, g_atl);
    cudaGetSymbolAddress((void**)&yT,  g_yT);
    cudaGetSymbolAddress((void**)&f,   g_f);
    cudaGetSymbolAddress((void**)&mean, g_mean); cudaGetSymbolAddress((void**)&rstd, g_rstd);

    const int SM3 = 4 * 49152;  // 196608
    const int SM2 = 4 * 32768;  // 131072
    cudaFuncSetAttribute((const void*)hgemm<0,3,1,2>, cudaFuncAttributeMaxDynamicSharedMemorySize, SM3);
    cudaFuncSetAttribute((const void*)hgemm<0,3,0,0>, cudaFuncAttributeMaxDynamicSharedMemorySize, SM3);
    cudaFuncSetAttribute((const void*)hgemm<1,2,2,1>, cudaFuncAttributeMaxDynamicSharedMemorySize, SM2);
    cudaFuncSetAttribute((const void*)hgemm<1,2,2,0>, cudaFuncAttributeMaxDynamicSharedMemorySize, SM2);
    cudaFuncSetAttribute((const void*)hgemm<1,2,0,1>, cudaFuncAttributeMaxDynamicSharedMemorySize, SM2);

    const long bs_xT = (long)NSP * CC;
    const long bs_pT = (long)NSP * CI;
    const long bs_g  = (long)CI * NSP;
    const long bs_f  = (long)NSP * NSP;
    const long bs_o  = (long)CC * NSP;

    // 0) weights split (one launch)
    wsplit_kernel<<<dim3((CI * CC) / 256, 4), 256>>>(
        Wt, Wp, Wg, Wo, Wth, Wtl, Wph, Wpl, Wgh, Wgl, Woh, Wol);
    // 1) x -> xT (bf16 h/l + fp16)
    xpose_split_kernel<<<dim3(NSP / 32, CC / 32, BB), 256>>>(x, xTbh, xTbl, xTf);

    // 2) g[ci][m] = Wg . xT + bg   (fp16 2-MMA, row bias, fp16 out)
    hgemm<1,2,2,1><<<dim3(NSP/256, CI/128, BB), 256, SM2>>>(
        Wgh, Wgl, xTf, nullptr, gf, nullptr, bg, CC, NSP, 0L, bs_xT, bs_g);
    // 3) thT[n][ci] = xT . Wt + bt  (bf16 3-MMA, col bias, bf16 h/l out)
    hgemm<0,3,1,2><<<dim3(CI/256, NSP/128, BB), 256, SM3>>>(
        xTbh, xTbl, Wth, Wtl, thh, thl, bt, CC, CI, bs_xT, 0L, bs_pT);
    // 4) phT
    hgemm<0,3,1,2><<<dim3(CI/256, NSP/128, BB), 256, SM3>>>(
        xTbh, xTbl, Wph, Wpl, phh, phl, bp, CC, CI, bs_xT, 0L, bs_pT);
    // 5) f[n][m] = thT . phT        (bf16 3-MMA, fp32 out)
    hgemm<0,3,0,0><<<dim3(NSP/256, NSP/128, BB), 256, SM3>>>(
        thh, thl, phh, phl, f, nullptr, nullptr, CI, NSP, bs_pT, bs_pT, bs_f);
    // 6) softmax -> attn fp16 h/l
    softmax_split_kernel<<<BB * NSP, 256>>>(f, ath, atl);
    // 7) yT[n][ci] = attn . g       (fp16 2-MMA, fp16 out)
    hgemm<1,2,2,0><<<dim3(CI/256, NSP/128, BB), 256, SM2>>>(
        ath, atl, gf, nullptr, yT, nullptr, nullptr, NSP, CI, bs_f, bs_g, bs_pT);
    // 8) out[o][n] = Wo . yT + bo   (fp16 2-MMA, fp32 -> d_out)
    hgemm<1,2,0,1><<<dim3(NSP/256, CC/128, BB), 256, SM2>>>(
        Woh, Wol, yT, nullptr, out, nullptr, bo, CI, NSP, 0L, bs_pT, bs_o);

    // 9) BN stats + apply + residual
    bn_stats_kernel<<<CC, 256>>>(out, mean, rstd);
    {
        const long total4 = (long)BB * CC * NSP / 4;
        bn_apply_kernel<<<(unsigned)(total4 / 256), 256>>>(out, x, mean, rstd, gamma, beta);
    }
}

// round 8
// speedup vs baseline: 1.1759x; 1.1759x over previous
#include <cuda_runtime.h>
#include <cuda_bf16.h>
#include <cuda_fp16.h>
#include <cstdint>
#include <math.h>

#define BB 64
#define CC 2048
#define CI 1024
#define NSP 512   // H*W

typedef unsigned short u16;
typedef uint32_t u32;

// ---------------- scratch (static device globals) -----------------------------
__device__ u16 g_xTh[(size_t)BB * NSP * CC];    // x^T fp16 hi [b][n][c]
__device__ u16 g_xTl[(size_t)BB * NSP * CC];    // x^T fp16 lo
__device__ u16 g_Wth[(size_t)CI * CC], g_Wtl[(size_t)CI * CC];   // fp16 h/l
__device__ u16 g_Wph[(size_t)CI * CC], g_Wpl[(size_t)CI * CC];   // fp16 h/l
__device__ u16 g_Wgf[(size_t)CI * CC];          // fp16 single
__device__ u16 g_Wof[(size_t)CC * CI];          // fp16 single
__device__ u16 g_thh[(size_t)BB * NSP * CI], g_thl[(size_t)BB * NSP * CI];
__device__ u16 g_phh[(size_t)BB * NSP * CI], g_phl[(size_t)BB * NSP * CI];
__device__ u16 g_gf [(size_t)BB * CI * NSP];    // g fp16 single [b][ci][m]
__device__ float g_f [(size_t)BB * NSP * NSP];  // f fp32
__device__ u16 g_ath[(size_t)BB * NSP * NSP];   // attn fp16 single
__device__ u16 g_yT [(size_t)BB * NSP * CI];    // y^T fp16 single
__device__ float g_mean[CC];
__device__ float g_rstd[CC];

// ---------------- helpers ------------------------------------------------------
__device__ __forceinline__ u32 smem_u32(const void* p) {
    u32 a;
    asm("{ .reg .u64 t; cvta.to.shared.u64 t, %1; cvt.u32.u64 %0, t; }" : "=r"(a) : "l"(p));
    return a;
}
__device__ __forceinline__ void split_fp(float v, u16& h, u16& l) {
    __half hh = __float2half_rn(v);
    h = __half_as_ushort(hh);
    l = __half_as_ushort(__float2half_rn(v - __half2float(hh)));
}
__device__ __forceinline__ void ldsm_x4(u32* r, u32 addr) {
    asm volatile("ldmatrix.sync.aligned.m8n8.x4.shared.b16 {%0,%1,%2,%3}, [%4];"
                 : "=r"(r[0]), "=r"(r[1]), "=r"(r[2]), "=r"(r[3]) : "r"(addr));
}
__device__ __forceinline__ void mma16816(float* c, const u32* a, u32 b0, u32 b1) {
    asm volatile("mma.sync.aligned.m16n8k16.row.col.f32.f16.f16.f32 "
                 "{%0,%1,%2,%3}, {%4,%5,%6,%7}, {%8,%9}, {%0,%1,%2,%3};"
                 : "+f"(c[0]), "+f"(c[1]), "+f"(c[2]), "+f"(c[3])
                 : "r"(a[0]), "r"(a[1]), "r"(a[2]), "r"(a[3]), "r"(b0), "r"(b1));
}

// copy ROWSx32 u16 chunk (row stride K) into blocked smem layout
template<int ROWS>
__device__ __forceinline__ void cpa(u32 dst, const u16* __restrict__ src,
                                    int K, int k0, int tid) {
    constexpr int RT  = ROWS / 8;
    constexpr int PER = (ROWS * 4) / 256;
#pragma unroll
    for (int i = 0; i < PER; ++i) {
        int u  = tid + i * 256;
        int r  = u >> 2;
        int kb = u & 3;
        const void* gp = src + (size_t)r * K + k0 + kb * 8;
        u32 dp = dst + (u32)(((kb * RT + (r >> 3)) << 7) + ((r & 7) << 4));
        asm volatile("cp.async.cg.shared.global [%0], [%1], 16;" :: "r"(dp), "l"(gp));
    }
}

// ---------------- HMMA GEMM (all fp16) ------------------------------------------
// D[m][n] = sum_k A[m][k]*B[n][k].
// NMMA=3: A h/l, B h/l, 3 terms (AhBh+AlBh+AhBl).  NMMA=1: A single, B single.
// CTA 128x256, 8 warps (2m x 4n), warp 64x64, k-chunk 32, 4 stages, 1 CTA/SM.
// OUT: 0 fp32, 1 fp16 hi/lo pair, 2 fp16 single.  BIAS: 0 none, 1 row(M), 2 col(N).
template<int NMMA, int OUT, int BIAS>
__global__ void __launch_bounds__(256, 1)
hgemm(const u16* __restrict__ Ah, const u16* __restrict__ Al,
      const u16* __restrict__ Bh, const u16* __restrict__ Bl,
      void* __restrict__ Co, u16* __restrict__ Colo,
      const float* __restrict__ bias,
      int K, int ldo, long bsA, long bsB, long bsC)
{
    extern __shared__ char smem[];
    const u32 sm0 = smem_u32(smem);
    constexpr u32 STAGE = (NMMA == 3) ? 49152u : 24576u;
    constexpr u32 BOFF  = (NMMA == 3) ? 16384u : 8192u;

    const int tid = threadIdx.x, lane = tid & 31, wid = tid >> 5;
    const int wm = wid >> 2, wn = wid & 3;
    const int m0 = blockIdx.y * 128, n0 = blockIdx.x * 256, b = blockIdx.z;

    const u16* pAh = Ah + (size_t)b * bsA + (size_t)m0 * K;
    const u16* pAl = (NMMA == 3) ? (Al + (size_t)b * bsA + (size_t)m0 * K) : nullptr;
    const u16* pBh = Bh + (size_t)b * bsB + (size_t)n0 * K;
    const u16* pBl = (NMMA == 3) ? (Bl + (size_t)b * bsB + (size_t)n0 * K) : nullptr;

    const int nch = K >> 5;

    float acc[4][8][4];
#pragma unroll
    for (int i = 0; i < 4; ++i)
#pragma unroll
        for (int j = 0; j < 8; ++j)
#pragma unroll
            for (int q = 0; q < 4; ++q) acc[i][j][q] = 0.f;

    // prologue: prefetch chunks 0..2
#pragma unroll
    for (int p = 0; p < 3; ++p) {
        u32 sb = sm0 + (u32)(p & 3) * STAGE;
        cpa<128>(sb, pAh, K, p * 32, tid);
        if (NMMA == 3) cpa<128>(sb + 8192, pAl, K, p * 32, tid);
        cpa<256>(sb + BOFF, pBh, K, p * 32, tid);
        if (NMMA == 3) cpa<256>(sb + 32768, pBl, K, p * 32, tid);
        asm volatile("cp.async.commit_group;");
    }

    const int ga = lane >> 3;
    const int lrow = lane & 7;

    for (int ks = 0; ks < nch; ++ks) {
        asm volatile("cp.async.wait_group 2;" ::: "memory");
        __syncthreads();
        {
            const int pf = ks + 3;
            if (pf < nch) {
                u32 sb = sm0 + (u32)(pf & 3) * STAGE;
                cpa<128>(sb, pAh, K, pf * 32, tid);
                if (NMMA == 3) cpa<128>(sb + 8192, pAl, K, pf * 32, tid);
                cpa<256>(sb + BOFF, pBh, K, pf * 32, tid);
                if (NMMA == 3) cpa<256>(sb + 32768, pBl, K, pf * 32, tid);
            }
            asm volatile("cp.async.commit_group;");
        }

        const u32 sb = sm0 + (u32)(ks & 3) * STAGE;
#pragma unroll
        for (int kk = 0; kk < 2; ++kk) {
            const int k8 = 2 * kk + (ga >> 1);
            // ---- A fragments ----
            u32 ah[4][4], al[4][4];
#pragma unroll
            for (int mf = 0; mf < 4; ++mf) {
                const int m8 = wm * 8 + mf * 2 + (ga & 1);
                u32 ad = sb + (u32)(((k8 * 16 + m8) << 7) + (lrow << 4));
                ldsm_x4(ah[mf], ad);
                if (NMMA == 3) ldsm_x4(al[mf], ad + 8192);
            }
            // ---- B fragments: double-buffered ----
            u32 bt[2][4], bs[2][4];
            {
                const int n8 = wn * 8 + (ga & 1);
                u32 bd = sb + BOFF + (u32)(((k8 * 32 + n8) << 7) + (lrow << 4));
                ldsm_x4(bt[0], bd);
                if (NMMA == 3) ldsm_x4(bs[0], bd + 16384u);
            }
#pragma unroll
            for (int np = 0; np < 4; ++np) {
                const int cur = np & 1;
                if (np < 3) {
                    const int n8 = wn * 8 + (np + 1) * 2 + (ga & 1);
                    u32 bd = sb + BOFF + (u32)(((k8 * 32 + n8) << 7) + (lrow << 4));
                    ldsm_x4(bt[cur ^ 1], bd);
                    if (NMMA == 3) ldsm_x4(bs[cur ^ 1], bd + 16384u);
                }
                // pass 1: ah * bt
#pragma unroll
                for (int mf = 0; mf < 4; ++mf) {
                    mma16816(acc[mf][2*np],   ah[mf], bt[cur][0], bt[cur][2]);
                    mma16816(acc[mf][2*np+1], ah[mf], bt[cur][1], bt[cur][3]);
                }
                if (NMMA == 3) {
                    // pass 2: al * bt
#pragma unroll
                    for (int mf = 0; mf < 4; ++mf) {
                        mma16816(acc[mf][2*np],   al[mf], bt[cur][0], bt[cur][2]);
                        mma16816(acc[mf][2*np+1], al[mf], bt[cur][1], bt[cur][3]);
                    }
                    // pass 3: ah * bs
#pragma unroll
                    for (int mf = 0; mf < 4; ++mf) {
                        mma16816(acc[mf][2*np],   ah[mf], bs[cur][0], bs[cur][2]);
                        mma16816(acc[mf][2*np+1], ah[mf], bs[cur][1], bs[cur][3]);
                    }
                }
            }
        }
    }

    // ---- epilogue ----
    const int erow = lane >> 2;
    const int ecol = (lane & 3) * 2;
#pragma unroll
    for (int mf = 0; mf < 4; ++mf) {
        const int gm = m0 + wm * 64 + mf * 16 + erow;
        float rb0 = 0.f, rb1 = 0.f;
        if (BIAS == 1) { rb0 = bias[gm]; rb1 = bias[gm + 8]; }
#pragma unroll
        for (int nf = 0; nf < 8; ++nf) {
            const int gn = n0 + wn * 64 + nf * 8 + ecol;
            float cb0 = 0.f, cb1 = 0.f;
            if (BIAS == 2) { cb0 = bias[gn]; cb1 = bias[gn + 1]; }
            float v00 = acc[mf][nf][0] + rb0 + cb0;
            float v01 = acc[mf][nf][1] + rb0 + cb1;
            float v10 = acc[mf][nf][2] + rb1 + cb0;
            float v11 = acc[mf][nf][3] + rb1 + cb1;
            if (OUT == 0) {
                float* C = (float*)Co + (size_t)b * bsC + (size_t)gm * ldo + gn;
                *reinterpret_cast<float2*>(C) = make_float2(v00, v01);
                *reinterpret_cast<float2*>(C + 8 * (size_t)ldo) = make_float2(v10, v11);
            } else if (OUT == 1) {
                u16* Ch = (u16*)Co + (size_t)b * bsC + (size_t)gm * ldo + gn;
                u16* Cl = Colo     + (size_t)b * bsC + (size_t)gm * ldo + gn;
                u16 h0, l0, h1, l1;
                split_fp(v00, h0, l0); split_fp(v01, h1, l1);
                *reinterpret_cast<u32*>(Ch) = (u32)h0 | ((u32)h1 << 16);
                *reinterpret_cast<u32*>(Cl) = (u32)l0 | ((u32)l1 << 16);
                split_fp(v10, h0, l0); split_fp(v11, h1, l1);
                *reinterpret_cast<u32*>(Ch + 8 * (size_t)ldo) = (u32)h0 | ((u32)h1 << 16);
                *reinterpret_cast<u32*>(Cl + 8 * (size_t)ldo) = (u32)l0 | ((u32)l1 << 16);
            } else {
                u16* C = (u16*)Co + (size_t)b * bsC + (size_t)gm * ldo + gn;
                u16 h0 = __half_as_ushort(__float2half_rn(v00));
                u16 h1 = __half_as_ushort(__float2half_rn(v01));
                *reinterpret_cast<u32*>(C) = (u32)h0 | ((u32)h1 << 16);
                h0 = __half_as_ushort(__float2half_rn(v10));
                h1 = __half_as_ushort(__float2half_rn(v11));
                *reinterpret_cast<u32*>(C + 8 * (size_t)ldo) = (u32)h0 | ((u32)h1 << 16);
            }
        }
    }
}

// ---------------- prepass: convert all 4 weights in ONE launch ------------------
__global__ void __launch_bounds__(256)
wsplit_kernel(const float* __restrict__ Wt, const float* __restrict__ Wp,
              const float* __restrict__ Wg, const float* __restrict__ Wo,
              u16* wth, u16* wtl, u16* wph, u16* wpl,
              u16* wgf, u16* wof)
{
    int i = blockIdx.x * 256 + threadIdx.x;
    u16 h, l;
    switch (blockIdx.y) {
        case 0: split_fp(Wt[i], h, l); wth[i] = h; wtl[i] = l; break;
        case 1: split_fp(Wp[i], h, l); wph[i] = h; wpl[i] = l; break;
        case 2: wgf[i] = __half_as_ushort(__float2half_rn(Wg[i])); break;
        default: wof[i] = __half_as_ushort(__float2half_rn(Wo[i])); break;
    }
}

// x [b][c][n] -> xT fp16 h/l [b][n][c]  (hi doubles as the single-precision copy)
__global__ void __launch_bounds__(256)
xpose_split_kernel(const float* __restrict__ x, u16* __restrict__ xh,
                   u16* __restrict__ xl) {
    __shared__ float t[32][33];
    const int b = blockIdx.z;
    const int n0 = blockIdx.x * 32, c0 = blockIdx.y * 32;
    const int tx = threadIdx.x & 31, ty = threadIdx.x >> 5;
    const float* xp = x + ((size_t)b * CC + c0) * NSP + n0;
#pragma unroll
    for (int i = 0; i < 4; ++i)
        t[ty + i * 8][tx] = xp[(size_t)(ty + i * 8) * NSP + tx];
    __syncthreads();
    const size_t ob = ((size_t)b * NSP + n0) * CC + c0;
#pragma unroll
    for (int i = 0; i < 4; ++i) {
        float v = t[tx][ty + i * 8];
        size_t idx = ob + (size_t)(ty + i * 8) * CC + tx;
        u16 h, l;
        split_fp(v, h, l);
        xh[idx] = h; xl[idx] = l;
    }
}

// ---------------- softmax over rows of 512 -> fp16 single -----------------------
__global__ void __launch_bounds__(256)
softmax_kernel(const float* __restrict__ f, u16* __restrict__ ah) {
    const size_t off = (size_t)blockIdx.x * NSP;
    const float* p = f + off;
    const int t = threadIdx.x;
    float v0 = p[t];
    float v1 = p[t + 256];

    __shared__ float red[8];
    float m = fmaxf(v0, v1);
#pragma unroll
    for (int o = 16; o; o >>= 1) m = fmaxf(m, __shfl_xor_sync(0xffffffffu, m, o));
    if ((t & 31) == 0) red[t >> 5] = m;
    __syncthreads();
    float M = red[0];
#pragma unroll
    for (int i = 1; i < 8; ++i) M = fmaxf(M, red[i]);
    __syncthreads();

    float e0 = expf(v0 - M);
    float e1 = expf(v1 - M);
    float s = e0 + e1;
#pragma unroll
    for (int o = 16; o; o >>= 1) s += __shfl_xor_sync(0xffffffffu, s, o);
    if ((t & 31) == 0) red[t >> 5] = s;
    __syncthreads();
    float S = 0.f;
#pragma unroll
    for (int i = 0; i < 8; ++i) S += red[i];

    const float inv = 1.f / S;
    ah[off + t]       = __half_as_ushort(__float2half_rn(e0 * inv));
    ah[off + t + 256] = __half_as_ushort(__float2half_rn(e1 * inv));
}

// ---------------- BN stats (fp32 accumulation) & apply --------------------------
__global__ void __launch_bounds__(256)
bn_stats_kernel(const float* __restrict__ wy, float* __restrict__ mean,
                float* __restrict__ rstd) {
    const int o = blockIdx.x;
    const int t = threadIdx.x;
    float ds = 0.f, dss = 0.f;
    for (int i = t; i < BB * NSP; i += 256) {
        const int b = i >> 9;
        const int n = i & (NSP - 1);
        const float v = wy[((size_t)b * CC + o) * NSP + n];
        ds  += v;
        dss = fmaf(v, v, dss);
    }
    __shared__ float r1[256];
    __shared__ float r2[256];
    r1[t] = ds; r2[t] = dss;
    __syncthreads();
    for (int st = 128; st; st >>= 1) {
        if (t < st) { r1[t] += r1[t + st]; r2[t] += r2[t + st]; }
        __syncthreads();
    }
    if (t == 0) {
        const double cnt = (double)(BB * NSP);
        const double mu  = (double)r1[0] / cnt;
        const double var = (double)r2[0] / cnt - mu * mu;
        mean[o] = (float)mu;
        rstd[o] = (float)rsqrt(var + 1e-5);
    }
}

__global__ void __launch_bounds__(256)
bn_apply_kernel(float* __restrict__ out, const float* __restrict__ x,
                const float* __restrict__ mean, const float* __restrict__ rstd,
                const float* __restrict__ gamma, const float* __restrict__ beta) {
    const long i4 = (long)blockIdx.x * blockDim.x + threadIdx.x;
    const long e = i4 * 4;
    const int c = (int)((e >> 9) & (CC - 1));
    const float mu = mean[c];
    const float rs = rstd[c];
    const float ga = gamma[c];
    const float be = beta[c];
    float4 w  = *reinterpret_cast<const float4*>(&out[e]);
    float4 xv = *reinterpret_cast<const float4*>(&x[e]);
    w.x = (w.x - mu) * rs * ga + be + xv.x;
    w.y = (w.y - mu) * rs * ga + be + xv.y;
    w.z = (w.z - mu) * rs * ga + be + xv.z;
    w.w = (w.w - mu) * rs * ga + be + xv.w;
    *reinterpret_cast<float4*>(&out[e]) = w;
}

// -------------------------------------------------------------------------------
extern "C" void kernel_launch(void* const* d_in, const int* in_sizes, int n_in,
                              void* d_out, int out_size)
{
    const float* x     = (const float*)d_in[0];
    const float* Wg    = (const float*)d_in[1];
    const float* bg    = (const float*)d_in[2];
    const float* Wt    = (const float*)d_in[3];
    const float* bt    = (const float*)d_in[4];
    const float* Wp    = (const float*)d_in[5];
    const float* bp    = (const float*)d_in[6];
    const float* Wo    = (const float*)d_in[7];
    const float* bo    = (const float*)d_in[8];
    const float* gamma = (const float*)d_in[9];
    const float* beta  = (const float*)d_in[10];
    float* out = (float*)d_out;

    u16 *xTh, *xTl, *Wth, *Wtl, *Wph, *Wpl, *Wgf, *Wof;
    u16 *thh, *thl, *phh, *phl, *gf, *ath, *yT;
    float *f, *mean, *rstd;
    cudaGetSymbolAddress((void**)&xTh, g_xTh); cudaGetSymbolAddress((void**)&xTl, g_xTl);
    cudaGetSymbolAddress((void**)&Wth, g_Wth); cudaGetSymbolAddress((void**)&Wtl, g_Wtl);
    cudaGetSymbolAddress((void**)&Wph, g_Wph); cudaGetSymbolAddress((void**)&Wpl, g_Wpl);
    cudaGetSymbolAddress((void**)&Wgf, g_Wgf); cudaGetSymbolAddress((void**)&Wof, g_Wof);
    cudaGetSymbolAddress((void**)&thh, g_thh); cudaGetSymbolAddress((void**)&thl, g_thl);
    cudaGetSymbolAddress((void**)&phh, g_phh); cudaGetSymbolAddress((void**)&phl, g_phl);
    cudaGetSymbolAddress((void**)&gf,  g_gf);
    cudaGetSymbolAddress((void**)&ath, g_ath);
    cudaGetSymbolAddress((void**)&yT,  g_yT);
    cudaGetSymbolAddress((void**)&f,   g_f);
    cudaGetSymbolAddress((void**)&mean, g_mean); cudaGetSymbolAddress((void**)&rstd, g_rstd);

    const int SM3 = 4 * 49152;  // 196608
    const int SM1 = 4 * 24576;  // 98304
    cudaFuncSetAttribute((const void*)hgemm<3,1,2>, cudaFuncAttributeMaxDynamicSharedMemorySize, SM3);
    cudaFuncSetAttribute((const void*)hgemm<3,0,0>, cudaFuncAttributeMaxDynamicSharedMemorySize, SM3);
    cudaFuncSetAttribute((const void*)hgemm<1,2,1>, cudaFuncAttributeMaxDynamicSharedMemorySize, SM1);
    cudaFuncSetAttribute((const void*)hgemm<1,2,0>, cudaFuncAttributeMaxDynamicSharedMemorySize, SM1);
    cudaFuncSetAttribute((const void*)hgemm<1,0,1>, cudaFuncAttributeMaxDynamicSharedMemorySize, SM1);

    const long bs_xT = (long)NSP * CC;
    const long bs_pT = (long)NSP * CI;
    const long bs_g  = (long)CI * NSP;
    const long bs_f  = (long)NSP * NSP;
    const long bs_o  = (long)CC * NSP;

    // 0) weights convert (one launch)
    wsplit_kernel<<<dim3((CI * CC) / 256, 4), 256>>>(
        Wt, Wp, Wg, Wo, Wth, Wtl, Wph, Wpl, Wgf, Wof);
    // 1) x -> xT fp16 h/l
    xpose_split_kernel<<<dim3(NSP / 32, CC / 32, BB), 256>>>(x, xTh, xTl);

    // 2) g[ci][m] = Wg . xT + bg   (1-MMA fp16, row bias, fp16 out)
    hgemm<1,2,1><<<dim3(NSP/256, CI/128, BB), 256, SM1>>>(
        Wgf, nullptr, xTh, nullptr, gf, nullptr, bg, CC, NSP, 0L, bs_xT, bs_g);
    // 3) thT[n][ci] = xT . Wt + bt  (3-MMA fp16, col bias, fp16 h/l out)
    hgemm<3,1,2><<<dim3(CI/256, NSP/128, BB), 256, SM3>>>(
        xTh, xTl, Wth, Wtl, thh, thl, bt, CC, CI, bs_xT, 0L, bs_pT);
    // 4) phT
    hgemm<3,1,2><<<dim3(CI/256, NSP/128, BB), 256, SM3>>>(
        xTh, xTl, Wph, Wpl, phh, phl, bp, CC, CI, bs_xT, 0L, bs_pT);
    // 5) f[n][m] = thT . phT        (3-MMA fp16, fp32 out)
    hgemm<3,0,0><<<dim3(NSP/256, NSP/128, BB), 256, SM3>>>(
        thh, thl, phh, phl, f, nullptr, nullptr, CI, NSP, bs_pT, bs_pT, bs_f);
    // 6) softmax -> attn fp16 single
    softmax_kernel<<<BB * NSP, 256>>>(f, ath);
    // 7) yT[n][ci] = attn . g       (1-MMA fp16, fp16 out)
    hgemm<1,2,0><<<dim3(CI/256, NSP/128, BB), 256, SM1>>>(
        ath, nullptr, gf, nullptr, yT, nullptr, nullptr, NSP, CI, bs_f, bs_g, bs_pT);
    // 8) out[o][n] = Wo . yT + bo   (1-MMA fp16, fp32 -> d_out)
    hgemm<1,0,1><<<dim3(NSP/256, CC/128, BB), 256, SM1>>>(
        Wof, nullptr, yT, nullptr, out, nullptr, bo, CI, NSP, 0L, bs_pT, bs_o);

    // 9) BN stats + apply + residual
    bn_stats_kernel<<<CC, 256>>>(out, mean, rstd);
    {
        const long total4 = (long)BB * CC * NSP / 4;
        bn_apply_kernel<<<(unsigned)(total4 / 256), 256>>>(out, x, mean, rstd, gamma, beta);
    }
}